// round 1
// baseline (speedup 1.0000x reference)
#include <cuda_runtime.h>

#define TPB 512

__device__ float g_loss[2048];
__device__ int   g_npos[2048];

__device__ __forceinline__ float warpReduceSumF(float v) {
#pragma unroll
    for (int o = 16; o; o >>= 1) v += __shfl_down_sync(0xffffffffu, v, o);
    return v;
}
__device__ __forceinline__ int warpReduceSumI(int v) {
#pragma unroll
    for (int o = 16; o; o >>= 1) v += __shfl_down_sync(0xffffffffu, v, o);
    return v;
}

__device__ __forceinline__ float blockReduceSumF(float v, float* sh) {
    int lane = threadIdx.x & 31, wid = threadIdx.x >> 5;
    int nw = (blockDim.x + 31) >> 5;
    v = warpReduceSumF(v);
    if (lane == 0) sh[wid] = v;
    __syncthreads();
    float r = 0.f;
    if (wid == 0) {
        r = (lane < nw) ? sh[lane] : 0.f;
        r = warpReduceSumF(r);
        if (lane == 0) sh[0] = r;
    }
    __syncthreads();
    r = sh[0];
    __syncthreads();
    return r;
}
__device__ __forceinline__ int blockReduceSumI(int v, int* sh) {
    int lane = threadIdx.x & 31, wid = threadIdx.x >> 5;
    int nw = (blockDim.x + 31) >> 5;
    v = warpReduceSumI(v);
    if (lane == 0) sh[wid] = v;
    __syncthreads();
    int r = 0;
    if (wid == 0) {
        r = (lane < nw) ? sh[lane] : 0;
        r = warpReduceSumI(r);
        if (lane == 0) sh[0] = r;
    }
    __syncthreads();
    r = sh[0];
    __syncthreads();
    return r;
}

// One CTA per batch element.
__global__ void mb_batch_kernel(const float* __restrict__ loc_pred,
                                const float* __restrict__ cls_pred,
                                const float* __restrict__ gt_boxes,
                                const int*   __restrict__ gt_labels,
                                const float* __restrict__ dbox,
                                int D, int M, int C)
{
    extern __shared__ unsigned char smraw[];
    const int b   = blockIdx.x;
    const int tid = threadIdx.x;
    const int T   = blockDim.x;

    size_t off = 0;
    float* s_ce  = (float*)(smraw + off); off += (size_t)D * 4;      // ov, then ce_neg
    short* s_obj = (short*)(smraw + off); off += (size_t)D * 2;
    off = (off + 7) & ~(size_t)7;
    float* s_gt  = (float*)(smraw + off); off += (size_t)M * 16;     // gt xyxy
    int* s_glab  = (int*)  (smraw + off); off += (size_t)M * 4;
    int* s_dpg   = (int*)  (smraw + off); off += (size_t)M * 4;
    float* s_redf= (float*)(smraw + off); off += 32 * 4;
    int* s_redi  = (int*)  (smraw + off);

    const float4* db4 = (const float4*)dbox;

    for (int i = tid; i < M * 4; i += T) s_gt[i] = gt_boxes[(size_t)b * M * 4 + i];
    for (int i = tid; i < M; i += T)     s_glab[i] = gt_labels[(size_t)b * M + i];
    __syncthreads();

    // ---- Phase A: per prior d, argmax IoU over gts (first-index on tie) ----
    for (int d = tid; d < D; d += T) {
        float4 p = db4[d];
        float px1 = p.x - p.z * 0.5f, py1 = p.y - p.w * 0.5f;
        float px2 = p.x + p.z * 0.5f, py2 = p.y + p.w * 0.5f;
        float pa = (px2 - px1) * (py2 - py1);
        float best = -1.f; int bi = 0;
        for (int m = 0; m < M; m++) {
            float gx1 = s_gt[m*4+0], gy1 = s_gt[m*4+1];
            float gx2 = s_gt[m*4+2], gy2 = s_gt[m*4+3];
            float w = fmaxf(fminf(gx2, px2) - fmaxf(gx1, px1), 0.f);
            float h = fmaxf(fminf(gy2, py2) - fmaxf(gy1, py1), 0.f);
            float inter = w * h;
            float ga = (gx2 - gx1) * (gy2 - gy1);
            float iou = inter / (ga + pa - inter);
            if (iou > best) { best = iou; bi = m; }
        }
        s_ce[d]  = best;       // overlaps_per_default
        s_obj[d] = (short)bi;  // objects_per_default
    }

    // ---- Phase B: per gt m, argmax IoU over priors (warp per gt, first-index) ----
    {
        int wid = tid >> 5, lane = tid & 31, NW = T >> 5;
        for (int m = wid; m < M; m += NW) {
            float gx1 = s_gt[m*4+0], gy1 = s_gt[m*4+1];
            float gx2 = s_gt[m*4+2], gy2 = s_gt[m*4+3];
            float ga = (gx2 - gx1) * (gy2 - gy1);
            float best = -1.f; int bd = 0;
            for (int d = lane; d < D; d += 32) {
                float4 p = db4[d];
                float px1 = p.x - p.z * 0.5f, py1 = p.y - p.w * 0.5f;
                float px2 = p.x + p.z * 0.5f, py2 = p.y + p.w * 0.5f;
                float pa = (px2 - px1) * (py2 - py1);
                float w = fmaxf(fminf(gx2, px2) - fmaxf(gx1, px1), 0.f);
                float h = fmaxf(fminf(gy2, py2) - fmaxf(gy1, py1), 0.f);
                float inter = w * h;
                float iou = inter / (ga + pa - inter);
                if (iou > best) { best = iou; bd = d; }
            }
#pragma unroll
            for (int o = 16; o; o >>= 1) {
                float ov = __shfl_down_sync(0xffffffffu, best, o);
                int   od = __shfl_down_sync(0xffffffffu, bd, o);
                if (ov > best || (ov == best && od < bd)) { best = ov; bd = od; }
            }
            if (lane == 0) s_dpg[m] = bd;
        }
    }
    __syncthreads();

    // ---- Phase C: force-match (sequential => last-write-wins in m order) ----
    if (tid == 0) {
        for (int m = 0; m < M; m++) {
            int dm = s_dpg[m];
            s_obj[dm] = (short)m;
            s_ce[dm]  = 1.0f;
        }
    }
    __syncthreads();

    // ---- Phase D+E fused: labels, encode + smooth-L1, log-softmax CE ----
    float loc_sum = 0.f, conf_pos = 0.f;
    int npos = 0;
    for (int d = tid; d < D; d += T) {
        int m = s_obj[d];
        float ov = s_ce[d];
        int lab = (ov < 0.5f) ? 0 : s_glab[m];

        if (lab > 0) {
            npos++;
            float gx1 = s_gt[m*4+0], gy1 = s_gt[m*4+1];
            float gx2 = s_gt[m*4+2], gy2 = s_gt[m*4+3];
            float gcx = (gx1 + gx2) * 0.5f, gcy = (gy1 + gy2) * 0.5f;
            float gw = gx2 - gx1, gh = gy2 - gy1;
            float4 p = db4[d];
            float e0 = (gcx - p.x) / (p.z / 10.0f);
            float e1 = (gcy - p.y) / (p.w / 10.0f);
            float e2 = logf(gw / p.z) * 5.0f;
            float e3 = logf(gh / p.w) * 5.0f;
            float4 lp = *(const float4*)(loc_pred + ((size_t)b * D + d) * 4);
            float dd, ad;
            dd = lp.x - e0; ad = fabsf(dd); loc_sum += (ad < 1.f) ? 0.5f*dd*dd : ad - 0.5f;
            dd = lp.y - e1; ad = fabsf(dd); loc_sum += (ad < 1.f) ? 0.5f*dd*dd : ad - 0.5f;
            dd = lp.z - e2; ad = fabsf(dd); loc_sum += (ad < 1.f) ? 0.5f*dd*dd : ad - 0.5f;
            dd = lp.w - e3; ad = fabsf(dd); loc_sum += (ad < 1.f) ? 0.5f*dd*dd : ad - 0.5f;
        }

        const float* cp = cls_pred + ((size_t)b * D + d) * C;
        float mx = cp[0];
        for (int c = 1; c < C; c++) mx = fmaxf(mx, cp[c]);
        float s = 0.f;
        for (int c = 0; c < C; c++) s += expf(cp[c] - mx);
        float ce = logf(s) - (cp[lab] - mx);

        if (lab > 0) { conf_pos += ce; s_ce[d] = 0.f; }
        else         { s_ce[d] = ce; }
    }
    __syncthreads();

    int   n_pos  = blockReduceSumI(npos, s_redi);
    float loc_b  = blockReduceSumF(loc_sum, s_redf);
    float conf_b = blockReduceSumF(conf_pos, s_redf);

    // ---- Phase F: hard-negative mining via bitwise top-k threshold ----
    float neg_sum = 0.f;
    int k = 3 * n_pos;
    if (k > 0) {
        unsigned thr = 0u;
        for (int bit = 30; bit >= 0; bit--) {
            unsigned cand = thr | (1u << bit);
            float cf = __uint_as_float(cand);
            int cnt = 0;
            for (int d = tid; d < D; d += T) cnt += (s_ce[d] >= cf) ? 1 : 0;
            cnt = blockReduceSumI(cnt, s_redi);
            if (cnt >= k) thr = cand;
        }
        float tf = __uint_as_float(thr);
        int cgt = 0; float sgt = 0.f;
        for (int d = tid; d < D; d += T) {
            float v = s_ce[d];
            if (v > tf) { cgt++; sgt += v; }
        }
        cgt = blockReduceSumI(cgt, s_redi);
        sgt = blockReduceSumF(sgt, s_redf);
        neg_sum = sgt + (float)(k - cgt) * tf;
    }

    if (tid == 0) {
        g_loss[b] = conf_b + neg_sum + loc_b;
        g_npos[b] = n_pos;
    }
}

__global__ void mb_finalize(float* __restrict__ out, int B)
{
    __shared__ float sf[32];
    __shared__ int si[32];
    float t = 0.f; int np = 0;
    for (int i = threadIdx.x; i < B; i += blockDim.x) {
        t += g_loss[i];
        np += g_npos[i];
    }
    t  = blockReduceSumF(t, sf);
    np = blockReduceSumI(np, si);
    if (threadIdx.x == 0) {
        int nt = np > 0 ? np : 1;
        out[0] = t / (float)nt;
    }
}

extern "C" void kernel_launch(void* const* d_in, const int* in_sizes, int n_in,
                              void* d_out, int out_size)
{
    const float* loc_pred = (const float*)d_in[0];
    const float* cls_pred = (const float*)d_in[1];
    const float* gt_boxes = (const float*)d_in[2];
    const int*   gt_labels= (const int*)  d_in[3];
    const float* dbox     = (const float*)d_in[4];

    int D = in_sizes[4] / 4;
    int B = in_sizes[0] / (D * 4);
    int C = (int)((long long)in_sizes[1] / ((long long)B * (long long)D));
    int M = in_sizes[2] / (B * 4);

    size_t sm = 0;
    sm += (size_t)D * 4;                 // s_ce
    sm += (size_t)D * 2;                 // s_obj
    sm = (sm + 7) & ~(size_t)7;
    sm += (size_t)M * 16;                // s_gt
    sm += (size_t)M * 4;                 // s_glab
    sm += (size_t)M * 4;                 // s_dpg
    sm += 32 * 4 + 32 * 4;               // reduce scratch

    cudaFuncSetAttribute(mb_batch_kernel,
                         cudaFuncAttributeMaxDynamicSharedMemorySize, (int)sm);

    mb_batch_kernel<<<B, TPB, sm>>>(loc_pred, cls_pred, gt_boxes, gt_labels,
                                    dbox, D, M, C);
    mb_finalize<<<1, 256>>>((float*)d_out, B);
}